// round 1
// baseline (speedup 1.0000x reference)
#include <cuda_runtime.h>
#include <math.h>
#include <float.h>

#define FS        16000.0f
#define N_FILT    80
#define FILT_DIM  251
#define HALF_K    125           // (FILT_DIM-1)/2
#define L_IN      32000
#define L_OUT     (L_IN - FILT_DIM + 1)   // 31750
#define BATCH     32

#define TILE_L    256
#define THREADS   512

// Half-filter coefficients (symmetric-pair weights), layout [k][f]:
//  k = 0..124 : weight applied to (x[l+k] + x[l+250-k])
//  k = 125    : center tap weight applied to x[l+125]
__device__ float g_filt[(HALF_K + 1) * N_FILT];

// ---------------------------------------------------------------------------
// Kernel 1: build filters, mirroring the JAX reference numerics.
// One block per filter, 128 threads.
// ---------------------------------------------------------------------------
__global__ void build_filters_kernel(const float* __restrict__ norm_f1,
                                     const float* __restrict__ norm_f2,
                                     const float* __restrict__ amplitude)
{
    const int f = blockIdx.x;
    const int t = threadIdx.x;

    const float min_n = 50.0f / FS;
    float f1n = fabsf(norm_f1[f]) + min_n;
    float f2n = f1n + fabsf(norm_f2[f] - f1n) + min_n;
    float f1 = f1n * FS;
    float f2 = f2n * FS;
    float amp = fabsf(amplitude[f]);

    __shared__ float bp[HALF_K];   // right-half band-pass (t index 0..124 => t_right)
    __shared__ float red[128];

    const float TWO_PI = 6.283185307179586f;

    float v = -FLT_MAX;
    if (t < HALF_K) {
        // t_right = (t+1)/fs, exact integers 1..125
        float tr = (float)(t + 1) / FS;
        float a2 = TWO_PI * f2 * tr;     // fp32 arg like reference
        float a1 = TWO_PI * f1 * tr;
        float s2 = (float)(sin((double)a2) / (double)a2);
        float s1 = (float)(sin((double)a1) / (double)a1);
        float b = amp * (2.0f * f2 * s2 - 2.0f * f1 * s1);
        bp[t] = b;
        v = b;
    }
    float center = amp * (2.0f * f2 - 2.0f * f1);  // sinc = 1 at center
    v = fmaxf(v, center);

    // block max reduction
    red[t] = v;
    __syncthreads();
    for (int s = 64; s > 0; s >>= 1) {
        if (t < s) red[t] = fmaxf(red[t], red[t + s]);
        __syncthreads();
    }
    float mx = red[0];

    // Window: w[j] = 0.54 - 0.46*cos(2*pi*j/250)   (n_j = j*251/250, /251)
    // Symmetric up to fp rounding; fold avg of the mirrored pair into g.
    for (int j = t; j <= HALF_K; j += blockDim.x) {
        float gv;
        if (j < HALF_K) {
            // full-filter tap j (j<125) = bp_right[124-j]
            double wj  = 0.54 - 0.46 * cos(2.0 * M_PI * (double)j / 250.0);
            double wjm = 0.54 - 0.46 * cos(2.0 * M_PI * (double)(250 - j) / 250.0);
            gv = (bp[HALF_K - 1 - j] / mx) * (float)(0.5 * (wj + wjm));
        } else {
            double wc = 0.54 - 0.46 * cos(2.0 * M_PI * 125.0 / 250.0);  // = 1.0
            gv = (center / mx) * (float)wc;
        }
        g_filt[j * N_FILT + f] = gv;
    }
}

// ---------------------------------------------------------------------------
// Kernel 2: symmetric conv. Block = (1 batch, 256 L, all 80 filters).
// 512 threads: warp id tf=0..15 owns 5 filters, lane tl=0..31 owns 8 L (stride 32).
// ---------------------------------------------------------------------------
__global__ void __launch_bounds__(THREADS, 1)
sinc_conv_kernel(const float* __restrict__ x, float* __restrict__ out)
{
    __shared__ float xs[TILE_L + FILT_DIM - 1];       // 506 floats
    __shared__ float gs[(HALF_K + 1) * N_FILT];       // 10080 floats = 40320 B

    const int b  = blockIdx.y;
    const int l0 = blockIdx.x * TILE_L;
    const int tid = threadIdx.x;

    // load filters into shared
    #pragma unroll 4
    for (int i = tid; i < (HALF_K + 1) * N_FILT; i += THREADS)
        gs[i] = g_filt[i];

    // load x tile (zero-pad past end of signal)
    const float* xb = x + (size_t)b * L_IN;
    for (int i = tid; i < TILE_L + FILT_DIM - 1; i += THREADS) {
        int gi = l0 + i;
        xs[i] = (gi < L_IN) ? xb[gi] : 0.0f;
    }
    __syncthreads();

    const int tf = tid >> 5;   // 0..15 (warp)
    const int tl = tid & 31;   // 0..31 (lane)

    float acc[5][8];
    #pragma unroll
    for (int i = 0; i < 5; i++)
        #pragma unroll
        for (int j = 0; j < 8; j++)
            acc[i][j] = 0.0f;

    const int fbase = tf * 5;

    #pragma unroll 5
    for (int k = 0; k < HALF_K; k++) {
        float s[8];
        #pragma unroll
        for (int j = 0; j < 8; j++) {
            int base = tl + j * 32;
            s[j] = xs[base + k] + xs[base + (FILT_DIM - 1) - k];
        }
        #pragma unroll
        for (int i = 0; i < 5; i++) {
            float gv = gs[k * N_FILT + fbase + i];   // warp-uniform broadcast
            #pragma unroll
            for (int j = 0; j < 8; j++)
                acc[i][j] = fmaf(gv, s[j], acc[i][j]);
        }
    }
    // center tap
    {
        float xc[8];
        #pragma unroll
        for (int j = 0; j < 8; j++)
            xc[j] = xs[tl + j * 32 + HALF_K];
        #pragma unroll
        for (int i = 0; i < 5; i++) {
            float gv = gs[HALF_K * N_FILT + fbase + i];
            #pragma unroll
            for (int j = 0; j < 8; j++)
                acc[i][j] = fmaf(gv, xc[j], acc[i][j]);
        }
    }

    // store (coalesced along l; guard last partial tile)
    #pragma unroll
    for (int i = 0; i < 5; i++) {
        int f = fbase + i;
        float* ob = out + ((size_t)b * N_FILT + f) * L_OUT + l0;
        #pragma unroll
        for (int j = 0; j < 8; j++) {
            int l = tl + j * 32;
            if (l0 + l < L_OUT) ob[l] = acc[i][j];
        }
    }
}

// ---------------------------------------------------------------------------
extern "C" void kernel_launch(void* const* d_in, const int* in_sizes, int n_in,
                              void* d_out, int out_size)
{
    const float* x       = (const float*)d_in[0];
    const float* norm_f1 = (const float*)d_in[1];
    const float* norm_f2 = (const float*)d_in[2];
    const float* ampl    = (const float*)d_in[3];
    float* out = (float*)d_out;

    build_filters_kernel<<<N_FILT, 128>>>(norm_f1, norm_f2, ampl);

    dim3 grid((L_OUT + TILE_L - 1) / TILE_L, BATCH);   // (125, 32)
    sinc_conv_kernel<<<grid, THREADS>>>(x, out);
}

// round 2
// speedup vs baseline: 1.2937x; 1.2937x over previous
#include <cuda_runtime.h>
#include <math.h>
#include <float.h>

#define FS        16000.0f
#define N_FILT    80
#define FILT_DIM  251
#define HALF_K    125           // (FILT_DIM-1)/2
#define L_IN      32000
#define L_OUT     (L_IN - FILT_DIM + 1)   // 31750
#define BATCH     32

#define TILE_L    256
#define THREADS   512
#define XS_LEN    (TILE_L + FILT_DIM - 1)   // 506

// Half-filter coefficients (symmetric-pair weights), layout [k][f]:
//  k = 0..124 : weight applied to (x[l+k] + x[l+250-k])
//  k = 125    : center tap weight applied to x[l+125]
__device__ float g_filt[(HALF_K + 1) * N_FILT];

// ---------------------------------------------------------------------------
// Kernel 1: build filters, mirroring the JAX reference numerics.
// ---------------------------------------------------------------------------
__global__ void build_filters_kernel(const float* __restrict__ norm_f1,
                                     const float* __restrict__ norm_f2,
                                     const float* __restrict__ amplitude)
{
    const int f = blockIdx.x;
    const int t = threadIdx.x;

    const float min_n = 50.0f / FS;
    float f1n = fabsf(norm_f1[f]) + min_n;
    float f2n = f1n + fabsf(norm_f2[f] - f1n) + min_n;
    float f1 = f1n * FS;
    float f2 = f2n * FS;
    float amp = fabsf(amplitude[f]);

    __shared__ float bp[HALF_K];
    __shared__ float red[128];

    const float TWO_PI = 6.283185307179586f;

    float v = -FLT_MAX;
    if (t < HALF_K) {
        float tr = (float)(t + 1) / FS;          // exact integers 1..125 / fs
        float a2 = TWO_PI * f2 * tr;             // fp32 arg like reference
        float a1 = TWO_PI * f1 * tr;
        float s2 = (float)(sin((double)a2) / (double)a2);
        float s1 = (float)(sin((double)a1) / (double)a1);
        float b = amp * (2.0f * f2 * s2 - 2.0f * f1 * s1);
        bp[t] = b;
        v = b;
    }
    float center = amp * (2.0f * f2 - 2.0f * f1);
    v = fmaxf(v, center);

    red[t] = v;
    __syncthreads();
    for (int s = 64; s > 0; s >>= 1) {
        if (t < s) red[t] = fmaxf(red[t], red[t + s]);
        __syncthreads();
    }
    float mx = red[0];

    for (int j = t; j <= HALF_K; j += blockDim.x) {
        float gv;
        if (j < HALF_K) {
            double wj  = 0.54 - 0.46 * cos(2.0 * M_PI * (double)j / 250.0);
            double wjm = 0.54 - 0.46 * cos(2.0 * M_PI * (double)(250 - j) / 250.0);
            gv = (bp[HALF_K - 1 - j] / mx) * (float)(0.5 * (wj + wjm));
        } else {
            gv = (center / mx);   // window = 1.0 at center
        }
        g_filt[j * N_FILT + f] = gv;
    }
}

// ---------------------------------------------------------------------------
// Kernel 2: symmetric conv, register sliding windows.
// Block = (1 batch, 256 L, all 80 filters). 512 threads.
// Warp tf owns filters [5*tf, 5*tf+5); lane tl owns L = [8*tl, 8*tl+8) in tile.
// ---------------------------------------------------------------------------
__global__ void __launch_bounds__(THREADS, 1)
sinc_conv_kernel(const float* __restrict__ x, float* __restrict__ out)
{
    __shared__ __align__(16) float xs[XS_LEN];                 // forward tile
    __shared__ __align__(16) float xr[XS_LEN];                 // reversed tile: xr[i] = xs[505-i]
    __shared__ float gs[(HALF_K + 1) * N_FILT];                // 40320 B

    const int b  = blockIdx.y;
    const int l0 = blockIdx.x * TILE_L;
    const int tid = threadIdx.x;

    #pragma unroll 4
    for (int i = tid; i < (HALF_K + 1) * N_FILT; i += THREADS)
        gs[i] = g_filt[i];

    const float* xb = x + (size_t)b * L_IN;
    for (int i = tid; i < XS_LEN; i += THREADS) {
        int gi = l0 + i;
        xs[i] = (gi < L_IN) ? xb[gi] : 0.0f;
        int gr = l0 + (XS_LEN - 1) - i;
        xr[i] = (gr < L_IN) ? xb[gr] : 0.0f;
    }
    __syncthreads();

    const int tf = tid >> 5;       // warp -> filter group
    const int tl = tid & 31;       // lane -> L chunk
    const int base  = tl * 8;      // tile-local L start (8-aligned)
    const int fbase = tf * 5;
    const int mb    = 248 - base;  // mirror window base in xr (8-aligned)

    float acc[5][8];
    #pragma unroll
    for (int i = 0; i < 5; i++)
        #pragma unroll
        for (int j = 0; j < 8; j++)
            acc[i][j] = 0.0f;

    float r[16], m[16];
    // prologue: r = xs[base .. base+15], m = xr[mb .. mb+15]
    #pragma unroll
    for (int q = 0; q < 4; q++) {
        float4 v = *(const float4*)&xs[base + 4 * q];
        r[4*q+0] = v.x; r[4*q+1] = v.y; r[4*q+2] = v.z; r[4*q+3] = v.w;
        float4 w = *(const float4*)&xr[mb + 4 * q];
        m[4*q+0] = w.x; m[4*q+1] = w.y; m[4*q+2] = w.z; m[4*q+3] = w.w;
    }

    // 15 chunks of 8 k-steps (k = 0..119)
    #pragma unroll 3
    for (int c = 0; c < 15; c++) {
        const int k0 = 8 * c;
        #pragma unroll
        for (int kk = 0; kk < 8; kk++) {
            float s[8];
            #pragma unroll
            for (int j = 0; j < 8; j++)
                s[j] = r[kk + j] + m[7 + kk - j];
            const int k = k0 + kk;
            #pragma unroll
            for (int i = 0; i < 5; i++) {
                float gv = gs[k * N_FILT + fbase + i];   // warp-uniform broadcast
                #pragma unroll
                for (int j = 0; j < 8; j++)
                    acc[i][j] = fmaf(gv, s[j], acc[i][j]);
            }
        }
        // slide both windows by 8
        #pragma unroll
        for (int t = 0; t < 8; t++) { r[t] = r[t + 8]; m[t] = m[t + 8]; }
        {
            float4 v0 = *(const float4*)&xs[base + k0 + 16];
            float4 v1 = *(const float4*)&xs[base + k0 + 20];
            r[8]=v0.x; r[9]=v0.y; r[10]=v0.z; r[11]=v0.w;
            r[12]=v1.x; r[13]=v1.y; r[14]=v1.z; r[15]=v1.w;
            float4 w0 = *(const float4*)&xr[mb + k0 + 16];
            float4 w1 = *(const float4*)&xr[mb + k0 + 20];
            m[8]=w0.x; m[9]=w0.y; m[10]=w0.z; m[11]=w0.w;
            m[12]=w1.x; m[13]=w1.y; m[14]=w1.z; m[15]=w1.w;
        }
    }

    // remainder k = 120..124 (windows now at k0 = 120)
    #pragma unroll
    for (int kk = 0; kk < 5; kk++) {
        float s[8];
        #pragma unroll
        for (int j = 0; j < 8; j++)
            s[j] = r[kk + j] + m[7 + kk - j];
        const int k = 120 + kk;
        #pragma unroll
        for (int i = 0; i < 5; i++) {
            float gv = gs[k * N_FILT + fbase + i];
            #pragma unroll
            for (int j = 0; j < 8; j++)
                acc[i][j] = fmaf(gv, s[j], acc[i][j]);
        }
    }
    // center tap k = 125 : x[base+125+j] = r[5+j]
    #pragma unroll
    for (int i = 0; i < 5; i++) {
        float gv = gs[HALF_K * N_FILT + fbase + i];
        #pragma unroll
        for (int j = 0; j < 8; j++)
            acc[i][j] = fmaf(gv, r[5 + j], acc[i][j]);
    }

    // store: 8 consecutive floats per filter per thread (float2: row stride
    // 31750 is only 8B aligned)
    const bool full = (l0 + TILE_L) <= L_OUT;
    #pragma unroll
    for (int i = 0; i < 5; i++) {
        float* ob = out + ((size_t)b * N_FILT + fbase + i) * L_OUT + l0 + base;
        if (full) {
            #pragma unroll
            for (int j = 0; j < 4; j++)
                *(float2*)(ob + 2 * j) = make_float2(acc[i][2*j], acc[i][2*j+1]);
        } else {
            #pragma unroll
            for (int j = 0; j < 8; j++)
                if (l0 + base + j < L_OUT) ob[j] = acc[i][j];
        }
    }
}

// ---------------------------------------------------------------------------
extern "C" void kernel_launch(void* const* d_in, const int* in_sizes, int n_in,
                              void* d_out, int out_size)
{
    const float* x       = (const float*)d_in[0];
    const float* norm_f1 = (const float*)d_in[1];
    const float* norm_f2 = (const float*)d_in[2];
    const float* ampl    = (const float*)d_in[3];
    float* out = (float*)d_out;

    build_filters_kernel<<<N_FILT, 128>>>(norm_f1, norm_f2, ampl);

    dim3 grid((L_OUT + TILE_L - 1) / TILE_L, BATCH);   // (125, 32)
    sinc_conv_kernel<<<grid, THREADS>>>(x, out);
}